// round 11
// baseline (speedup 1.0000x reference)
#include <cuda_runtime.h>
#include <math.h>

// BackupBarrierCBF — closed-form per-corner argmin; 2 independent elements per
// thread for ILP (latency-bound regime: interleaved chains, no extra instr/elem).
#define T_LO 1.0f
#define T_HI 50.0f

#define THREADS 128
#define ELEMS_PER_BLOCK 256                       // 2 per thread
#define FLOATS_PER_BLOCK (ELEMS_PER_BLOCK * 15)   // 3840 floats = 960 float4

__device__ __forceinline__ float tanh_approx(float x) {
    float y;
    asm("tanh.approx.f32 %0, %1;" : "=f"(y) : "f"(x));
    return y;
}

// Full per-element pipeline: smem -> h (pre-sigmoid min distance).
__device__ __forceinline__ float cbf_elem(const float* __restrict__ pp) {
    float exg  = pp[0],  eyg  = pp[1],  eyaw = pp[2],  ev = pp[3];
    float axg  = pp[4],  ayg  = pp[5],  ayaw = pp[6],  av = pp[7];
    float eL   = pp[8],  eW   = pp[9];
    float aL   = pp[11], aW   = pp[12];
    float dt   = pp[14];

    float se, ce, sa, ca;
    __sincosf(eyaw, &se, &ce);
    __sincosf(ayaw, &sa, &ca);

    // Relative velocity per step, rotated into the (time-invariant) ego frame.
    float dvx = dt * (av * ca - ev * ce);
    float dvy = dt * (av * sa - ev * se);
    float p   =  dvx * ce + dvy * se;
    float q   = -dvx * se + dvy * ce;
    float ap  = fabsf(p), aq = fabsf(q);
    float rp  = __fdividef(1.0f, p);
    float rq  = __fdividef(1.0f, q);
    float rs  = __fdividef(1.0f, ap + aq);

    // Relative center at t=0, ego frame.
    float rx0 = axg - exg, ry0 = ayg - eyg;
    float Xc  =  rx0 * ce + ry0 * se;
    float Yc  = -rx0 * se + ry0 * ce;

    // Agent box half-axes in the ego frame (rotation by ayaw - eyaw).
    float cd = ca * ce + sa * se;
    float sd = sa * ce - ca * se;
    float hx = 0.5f * aL, hy = 0.5f * aW;
    float ux =  hx * cd, uy = hx * sd;
    float vx = -hy * sd, vy = hy * cd;

    const float kx  = 0.5f * eL + 1.0f;   // OFFSET_X
    const float ky  = 0.5f * eW + 0.3f;   // OFFSET_Y
    const float cdk = kx - ky;
    const float nkx = -kx, nky = -ky;

    float hacc[4];

    #pragma unroll
    for (int i = 0; i < 4; ++i) {
        float X = (i < 2) ? (Xc + ux) : (Xc - ux);
        float Y = (i < 2) ? (Yc + uy) : (Yc - uy);
        if (i & 1) { X -= vx; Y -= vy; } else { X += vx; Y += vy; }

        float t1 = -X * rp;                        // vertex of |X+pt|
        float t2 = -Y * rq;                        // vertex of |Y+qt|
        float g2t1 = fabsf(fmaf(q, t1, Y)) + nky;  // g2 at t1
        float g1t2 = fabsf(fmaf(p, t2, X)) + nkx;  // g1 at t2

        // Crossing of the two V-shapes between the vertices.
        float csn  = (t2 >= t1) ? cdk : -cdk;
        float tint = fmaf(ap, t1, fmaf(aq, t2, csn)) * rs;

        // Closed-form continuous argmin (NaN comparisons fall through safely).
        float ts = (g2t1 <= nkx) ? t1 : ((g1t2 <= nky) ? t2 : tint);
        ts = fminf(fmaxf(ts, T_LO), T_HI);         // NaN -> T_LO

        float tf = floorf(ts);
        float te = fminf(tf + 1.0f, T_HI);
        float m0 = fmaxf(fabsf(fmaf(p, tf, X)) + nkx,
                         fabsf(fmaf(q, tf, Y)) + nky);
        float m1 = fmaxf(fabsf(fmaf(p, te, X)) + nkx,
                         fabsf(fmaf(q, te, Y)) + nky);
        hacc[i] = fminf(m0, m1);
    }

    return fminf(fminf(hacc[0], hacc[1]), fminf(hacc[2], hacc[3]));
}

__global__ __launch_bounds__(THREADS)
void cbf_kernel(const float* __restrict__ data, float* __restrict__ out, int n) {
    __shared__ float sm[FLOATS_PER_BLOCK];

    int e0 = blockIdx.x * ELEMS_PER_BLOCK;

    // Stage 256 elements = 960 float4, fully coalesced (block base 16B-aligned:
    // 256*15*4 = 15360 bytes per block).
    {
        const float4* g4 = (const float4*)(data + (size_t)e0 * 15);
        float4* s4 = (float4*)sm;
        #pragma unroll
        for (int i = threadIdx.x; i < FLOATS_PER_BLOCK / 4; i += THREADS)
            s4[i] = g4[i];
    }
    __syncthreads();

    int t = threadIdx.x;

    // Two fully independent element pipelines — compiler interleaves them,
    // doubling latency overlap at zero extra instructions per element.
    float h0 = cbf_elem(sm + t * 15);
    float h1 = cbf_elem(sm + (t + THREADS) * 15);

    // (sigmoid(h/5) - 0.5) * 10 == 5 * tanh(h/10)
    out[e0 + t]           = 5.0f * tanh_approx(h0 * 0.1f);
    out[e0 + t + THREADS] = 5.0f * tanh_approx(h1 * 0.1f);
}

extern "C" void kernel_launch(void* const* d_in, const int* in_sizes, int n_in,
                              void* d_out, int out_size) {
    const float* data = (const float*)d_in[0];
    float* out = (float*)d_out;
    int n = out_size;                  // B*A = 131072, multiple of 256
    int blocks = (n + ELEMS_PER_BLOCK - 1) / ELEMS_PER_BLOCK;   // 512
    cbf_kernel<<<blocks, THREADS>>>(data, out, n);
}

// round 12
// speedup vs baseline: 1.0048x; 1.0048x over previous
#include <cuda_runtime.h>
#include <math.h>

// BackupBarrierCBF — closed-form per-corner argmin, delta-yaw simplification,
// warp-private smem staging (no block barrier), tanh.approx epilogue.
//
// Math: in the (time-invariant) ego frame, relative corner position is affine
// in t with slopes shared by all 4 corners:
//   p = dt*(av*cos(dyaw) - ev),  q = dt*av*sin(dyaw),  dyaw = ayaw - eyaw
// f(t) = max(|X+pt|-kx, |Y+qt|-ky) is a max of two V-shapes; continuous argmin
// is vertex t1, vertex t2, or their crossing (2 comparisons). Discrete argmin
// over t in [1,50] is floor/ceil of the clamped continuous argmin.
#define T_LO 1.0f
#define T_HI 50.0f

#define THREADS 128
#define ELEMS_PER_BLOCK 128
#define FLOATS_PER_WARP (32 * 15)     // 480 floats = 120 float4 per warp

__device__ __forceinline__ float tanh_approx(float x) {
    float y;
    asm("tanh.approx.f32 %0, %1;" : "=f"(y) : "f"(x));
    return y;
}

__global__ __launch_bounds__(THREADS)
void cbf_kernel(const float* __restrict__ data, float* __restrict__ out, int n) {
    __shared__ float sm[ELEMS_PER_BLOCK * 15];

    int e0   = blockIdx.x * ELEMS_PER_BLOCK;
    int warp = threadIdx.x >> 5;
    int lane = threadIdx.x & 31;

    // Warp-private staging: each warp loads its own 32 elements (1920 B,
    // 16B-aligned since 32*15*4 = 1920). Only __syncwarp needed — no
    // block-wide barrier, warps proceed independently.
    {
        const float4* g4 = (const float4*)(data + (size_t)(e0 + warp * 32) * 15);
        float4* s4 = (float4*)(sm + warp * FLOATS_PER_WARP);
        #pragma unroll
        for (int i = lane; i < FLOATS_PER_WARP / 4; i += 32)   // 120 -> 4 iters
            s4[i] = g4[i];
    }
    __syncwarp();

    const float* pp = sm + threadIdx.x * 15;   // stride 15: conflict-free
    float exg  = pp[0],  eyg  = pp[1],  eyaw = pp[2],  ev = pp[3];
    float axg  = pp[4],  ayg  = pp[5],  ayaw = pp[6],  av = pp[7];
    float eL   = pp[8],  eW   = pp[9];
    float aL   = pp[11], aW   = pp[12];
    float dt   = pp[14];

    float se, ce, sd, cd;
    __sincosf(eyaw, &se, &ce);
    __sincosf(ayaw - eyaw, &sd, &cd);    // delta yaw: drives p,q and corner axes

    // Per-step relative velocity in the ego frame (closed form via dyaw).
    float p  = dt * fmaf(av, cd, -ev);
    float q  = dt * (av * sd);
    float ap = fabsf(p), aq = fabsf(q);
    float rp = __fdividef(1.0f, p);
    float rq = __fdividef(1.0f, q);
    float rs = __fdividef(1.0f, ap + aq);

    // Relative center at t=0 in the ego frame.
    float rx0 = axg - exg, ry0 = ayg - eyg;
    float Xc  =  rx0 * ce + ry0 * se;
    float Yc  = -rx0 * se + ry0 * ce;

    // Agent half-axes in the ego frame (rotation by dyaw).
    float hx = 0.5f * aL, hy = 0.5f * aW;
    float ux =  hx * cd, uy = hx * sd;
    float vx = -hy * sd, vy = hy * cd;

    const float kx  = 0.5f * eL + 1.0f;   // OFFSET_X
    const float ky  = 0.5f * eW + 0.3f;   // OFFSET_Y
    const float cdk = kx - ky;
    const float nkx = -kx, nky = -ky;

    float hacc[4];

    #pragma unroll
    for (int i = 0; i < 4; ++i) {
        float X = (i < 2) ? (Xc + ux) : (Xc - ux);
        float Y = (i < 2) ? (Yc + uy) : (Yc - uy);
        if (i & 1) { X -= vx; Y -= vy; } else { X += vx; Y += vy; }

        float t1 = -X * rp;                        // vertex of |X+pt|
        float t2 = -Y * rq;                        // vertex of |Y+qt|
        float g2t1 = fabsf(fmaf(q, t1, Y)) + nky;  // g2 at t1
        float g1t2 = fabsf(fmaf(p, t2, X)) + nkx;  // g1 at t2

        // Crossing of the two V-shapes between the vertices.
        float csn  = (t2 >= t1) ? cdk : -cdk;
        float tint = fmaf(ap, t1, fmaf(aq, t2, csn)) * rs;

        // Closed-form continuous argmin (NaN comparisons fall through safely).
        float ts = (g2t1 <= nkx) ? t1 : ((g1t2 <= nky) ? t2 : tint);
        ts = fminf(fmaxf(ts, T_LO), T_HI);         // NaN -> T_LO

        float tf = floorf(ts);
        float te = fminf(tf + 1.0f, T_HI);
        float x0 = fmaf(p, tf, X), y0 = fmaf(q, tf, Y);
        float m0 = fmaxf(fabsf(x0) + nkx, fabsf(y0) + nky);
        float m1 = fmaxf(fabsf(fmaf(p, te, X)) + nkx,
                         fabsf(fmaf(q, te, Y)) + nky);
        hacc[i] = fminf(m0, m1);
    }

    float hm = fminf(fminf(hacc[0], hacc[1]), fminf(hacc[2], hacc[3]));

    // (sigmoid(h/5) - 0.5) * 10 == 5 * tanh(h/10)
    out[e0 + threadIdx.x] = 5.0f * tanh_approx(hm * 0.1f);
}

extern "C" void kernel_launch(void* const* d_in, const int* in_sizes, int n_in,
                              void* d_out, int out_size) {
    const float* data = (const float*)d_in[0];
    float* out = (float*)d_out;
    int n = out_size;                  // B*A = 131072
    int blocks = (n + ELEMS_PER_BLOCK - 1) / ELEMS_PER_BLOCK;   // 1024
    cbf_kernel<<<blocks, THREADS>>>(data, out, n);
}

// round 13
// speedup vs baseline: 1.0097x; 1.0049x over previous
#include <cuda_runtime.h>
#include <math.h>

// BackupBarrierCBF — closed-form per-corner argmin, delta-yaw form,
// 2 independent elements per thread WITH register headroom
// (__launch_bounds__(128,1)) so ptxas keeps both pipelines live (ILP x2).
#define T_LO 1.0f
#define T_HI 50.0f

#define THREADS 128
#define ELEMS_PER_BLOCK 256                    // 2 per thread
#define FLOATS_PER_WARP (64 * 15)              // warp stages 64 elems = 240 float4

__device__ __forceinline__ float tanh_approx(float x) {
    float y;
    asm("tanh.approx.f32 %0, %1;" : "=f"(y) : "f"(x));
    return y;
}

// Per-element pipeline: smem row -> h (pre-sigmoid min corner distance).
__device__ __forceinline__ float cbf_elem(const float* __restrict__ pp) {
    float exg  = pp[0],  eyg  = pp[1],  eyaw = pp[2],  ev = pp[3];
    float axg  = pp[4],  ayg  = pp[5],  ayaw = pp[6],  av = pp[7];
    float eL   = pp[8],  eW   = pp[9];
    float aL   = pp[11], aW   = pp[12];
    float dt   = pp[14];

    float se, ce, sd, cd;
    __sincosf(eyaw, &se, &ce);
    __sincosf(ayaw - eyaw, &sd, &cd);          // delta yaw

    // Per-step relative velocity in the ego frame (closed form via dyaw).
    float p  = dt * fmaf(av, cd, -ev);
    float q  = dt * (av * sd);
    float ap = fabsf(p), aq = fabsf(q);
    float rp = __fdividef(1.0f, p);
    float rq = __fdividef(1.0f, q);
    float rs = __fdividef(1.0f, ap + aq);

    // Relative center at t=0 in the ego frame.
    float rx0 = axg - exg, ry0 = ayg - eyg;
    float Xc  =  rx0 * ce + ry0 * se;
    float Yc  = -rx0 * se + ry0 * ce;

    // Agent half-axes in the ego frame (rotation by dyaw).
    float hx = 0.5f * aL, hy = 0.5f * aW;
    float ux =  hx * cd, uy = hx * sd;
    float vx = -hy * sd, vy = hy * cd;

    const float kx  = 0.5f * eL + 1.0f;        // OFFSET_X
    const float ky  = 0.5f * eW + 0.3f;        // OFFSET_Y
    const float cdk = kx - ky;
    const float nkx = -kx, nky = -ky;

    float hacc[4];

    #pragma unroll
    for (int i = 0; i < 4; ++i) {
        float X = (i < 2) ? (Xc + ux) : (Xc - ux);
        float Y = (i < 2) ? (Yc + uy) : (Yc - uy);
        if (i & 1) { X -= vx; Y -= vy; } else { X += vx; Y += vy; }

        float t1 = -X * rp;                        // vertex of |X+pt|
        float t2 = -Y * rq;                        // vertex of |Y+qt|
        float g2t1 = fabsf(fmaf(q, t1, Y)) + nky;  // g2 at t1
        float g1t2 = fabsf(fmaf(p, t2, X)) + nkx;  // g1 at t2

        // Crossing of the two V-shapes between the vertices.
        float csn  = (t2 >= t1) ? cdk : -cdk;
        float tint = fmaf(ap, t1, fmaf(aq, t2, csn)) * rs;

        // Closed-form continuous argmin (NaN comparisons fall through safely).
        float ts = (g2t1 <= nkx) ? t1 : ((g1t2 <= nky) ? t2 : tint);
        ts = fminf(fmaxf(ts, T_LO), T_HI);         // NaN -> T_LO

        float tf = floorf(ts);
        float te = fminf(tf + 1.0f, T_HI);
        float m0 = fmaxf(fabsf(fmaf(p, tf, X)) + nkx,
                         fabsf(fmaf(q, tf, Y)) + nky);
        float m1 = fmaxf(fabsf(fmaf(p, te, X)) + nkx,
                         fabsf(fmaf(q, te, Y)) + nky);
        hacc[i] = fminf(m0, m1);
    }

    return fminf(fminf(hacc[0], hacc[1]), fminf(hacc[2], hacc[3]));
}

__global__ __launch_bounds__(THREADS, 1)       // allow high reg count: keep
void cbf_kernel(const float* __restrict__ data,//  both element pipelines live
                float* __restrict__ out, int n) {
    __shared__ float sm[ELEMS_PER_BLOCK * 15];

    int e0   = blockIdx.x * ELEMS_PER_BLOCK;
    int warp = threadIdx.x >> 5;
    int lane = threadIdx.x & 31;

    // Warp-private staging: each warp loads its own 64 elements (3840 B,
    // 16B-aligned: 64*15*4). 240 float4 / 32 lanes = 7.5 -> 8 front-batched
    // LDG.128 per lane (high MLP at the memory front).
    {
        const float4* g4 = (const float4*)(data + (size_t)(e0 + warp * 64) * 15);
        float4* s4 = (float4*)(sm + warp * FLOATS_PER_WARP);
        #pragma unroll
        for (int i = lane; i < FLOATS_PER_WARP / 4; i += 32)
            s4[i] = g4[i];
    }
    __syncwarp();

    int ebase = warp * 64 + lane;              // element within block, first half

    // Two fully independent pipelines; with reg headroom ptxas interleaves them.
    float h0 = cbf_elem(sm + ebase * 15);
    float h1 = cbf_elem(sm + (ebase + 32) * 15);

    // (sigmoid(h/5) - 0.5) * 10 == 5 * tanh(h/10)
    out[e0 + ebase]      = 5.0f * tanh_approx(h0 * 0.1f);
    out[e0 + ebase + 32] = 5.0f * tanh_approx(h1 * 0.1f);
}

extern "C" void kernel_launch(void* const* d_in, const int* in_sizes, int n_in,
                              void* d_out, int out_size) {
    const float* data = (const float*)d_in[0];
    float* out = (float*)d_out;
    int n = out_size;                  // B*A = 131072, multiple of 256
    int blocks = (n + ELEMS_PER_BLOCK - 1) / ELEMS_PER_BLOCK;   // 512
    cbf_kernel<<<blocks, THREADS>>>(data, out, n);
}